// round 4
// baseline (speedup 1.0000x reference)
#include <cuda_runtime.h>
#include <cuda_bf16.h>
#include <cstdint>

#define BB   16
#define TT   128
#define VV   32000
#define HH   512
#define LL   2
#define DD   8
#define AH   256
#define G4   2048
#define PAD_ID 0
#define EOS_ID 3
#define NROW (BB*TT)            // 2048
#define BTV  ((size_t)NROW*VV)

// ---------------- device scratch ----------------
__device__ float g_scores[BB*DD*LL];
__device__ float g_ctx[BB*LL*HH];
__device__ float g_K[LL*BB*G4];
__device__ float g_Xe[NROW*HH];
__device__ float g_gx0[(size_t)NROW*G4];
__device__ float g_X[NROW*HH];
__device__ float g_h0[2][BB*HH];
__device__ float g_h1[2][BB*HH];
__device__ float g_c0[BB*HH];
__device__ float g_c1[BB*HH];
__device__ float g_rowmax[NROW];
__device__ int   g_argidx[NROW];
__device__ int   g_mask[NROW];
__device__ unsigned g_bcnt = 0;
__device__ unsigned g_bgen = 0;

__device__ __forceinline__ float sigf(float x){ return 1.0f/(1.0f+__expf(-x)); }

// grid barrier (all CTAs resident)
__device__ __forceinline__ void gbar() {
    __threadfence();
    __syncthreads();
    if (threadIdx.x == 0) {
        volatile unsigned* vg = &g_bgen;
        unsigned g = *vg;
        unsigned a = atomicAdd(&g_bcnt, 1u);
        if (a == gridDim.x - 1u) {
            g_bcnt = 0;
            __threadfence();
            atomicAdd(&g_bgen, 1u);
        } else {
            while (*vg == g) { __nanosleep(64); }
        }
        __threadfence();
    }
    __syncthreads();
}

// ---------------- K1: attention scores  blk=(b*D+d)*L+l ----------------
__global__ void k_attn_scores(const float* __restrict__ emb, const float* __restrict__ W1,
                              const float* __restrict__ b1, const float* __restrict__ W2,
                              const float* __restrict__ b2) {
    __shared__ float se[HH];
    __shared__ float red[AH];
    int blk = blockIdx.x;
    const float* ep = emb + (size_t)blk * HH;
    for (int i = threadIdx.x; i < HH; i += AH) se[i] = ep[i];
    __syncthreads();
    int a = threadIdx.x;
    const float* w1 = W1 + (size_t)a * HH;
    float dot = 0.f;
    #pragma unroll 8
    for (int k = 0; k < HH; k++) dot += se[k] * w1[k];
    red[a] = tanhf(dot + b1[a]) * W2[a];
    __syncthreads();
    for (int s = AH/2; s > 0; s >>= 1) {
        if (a < s) red[a] += red[a + s];
        __syncthreads();
    }
    if (a == 0) g_scores[blk] = red[0] + b2[0];
}

// ---------------- K2: softmax over docs + context ----------------
__global__ void k_attn_ctx(const float* __restrict__ emb) {
    int b = blockIdx.x >> 1, l = blockIdx.x & 1;
    __shared__ float s[DD];
    if (threadIdx.x < DD) s[threadIdx.x] = g_scores[(b*DD + threadIdx.x)*LL + l];
    __syncthreads();
    float mx = -1e30f;
    #pragma unroll
    for (int d = 0; d < DD; d++) mx = fmaxf(mx, s[d]);
    float w[DD]; float sum = 0.f;
    #pragma unroll
    for (int d = 0; d < DD; d++) { w[d] = __expf(s[d] - mx); sum += w[d]; }
    float inv = 1.0f / sum;
    for (int h = threadIdx.x; h < HH; h += 256) {
        float acc = 0.f;
        #pragma unroll
        for (int d = 0; d < DD; d++)
            acc += w[d] * inv * emb[((size_t)(b*DD + d)*LL + l)*HH + h];
        g_ctx[(b*LL + l)*HH + h] = acc;
    }
}

// ---------------- K3: K[l][b][g] = 0.5*ctx@Whh^T + b_ih + b_hh ----------------
__global__ void k_ctx_gates(const float* __restrict__ Whh, const float* __restrict__ bih,
                            const float* __restrict__ bhh) {
    int out  = blockIdx.x * 8 + (threadIdx.x >> 5);
    int lane = threadIdx.x & 31;
    int l = out >> 15;
    int b = (out >> 11) & 15;
    int g = out & 2047;
    const float* wr = Whh + (size_t)l*G4*HH + (size_t)g*HH;
    const float* cx = g_ctx + (b*LL + l)*HH;
    float acc = 0.f;
    for (int k = lane; k < HH; k += 32) acc += wr[k]*cx[k];
    #pragma unroll
    for (int o = 16; o > 0; o >>= 1) acc += __shfl_xor_sync(0xffffffffu, acc, o);
    if (lane == 0) g_K[out] = 0.5f*acc + bih[l*G4 + g] + bhh[l*G4 + g];
}

// ---------------- K4: embedding gather ----------------
__global__ void k_embed(const int* __restrict__ init_input, const int* __restrict__ targets,
                        const float* __restrict__ embW) {
    int i4 = blockIdx.x * 256 + threadIdx.x;       // over B*T*H/4
    if (i4 >= BB*TT*HH/4) return;
    int r  = i4 >> 7;
    int h4 = i4 & 127;
    int b = r >> 7, t = r & 127;
    int tok = (t == 0) ? init_input[b] : targets[b*TT + t - 1];
    ((float4*)g_Xe)[i4] = ((const float4*)(embW + (size_t)tok*HH))[h4];
}

// ---------------- SGEMM NT: C[m][n] = sum_k A[m][k]*B[n][k] (+bias) ----------------
__global__ __launch_bounds__(256) void k_sgemm_nt(int mode, const float* __restrict__ Bw,
                                                  const float* __restrict__ bias,
                                                  float* __restrict__ Cout, int N) {
    const float* A = (mode == 0) ? g_Xe : g_X;
    float* C = (mode == 0) ? g_gx0 : Cout;

    __shared__ float As[8][128];
    __shared__ float Bs[8][128];
    int tid = threadIdx.x;
    int aRow = tid >> 1, aCol = (tid & 1) << 2;
    const float* Ap = A  + ((size_t)blockIdx.y*128 + aRow)*HH + aCol;
    const float* Bp = Bw + ((size_t)blockIdx.x*128 + aRow)*HH + aCol;
    int tx = tid & 15, ty = tid >> 4;

    float acc[8][8];
    #pragma unroll
    for (int i = 0; i < 8; i++)
        #pragma unroll
        for (int j = 0; j < 8; j++) acc[i][j] = 0.f;

    for (int k0 = 0; k0 < HH; k0 += 8) {
        float4 av = *(const float4*)(Ap + k0);
        float4 bv = *(const float4*)(Bp + k0);
        As[aCol+0][aRow] = av.x; As[aCol+1][aRow] = av.y;
        As[aCol+2][aRow] = av.z; As[aCol+3][aRow] = av.w;
        Bs[aCol+0][aRow] = bv.x; Bs[aCol+1][aRow] = bv.y;
        Bs[aCol+2][aRow] = bv.z; Bs[aCol+3][aRow] = bv.w;
        __syncthreads();
        #pragma unroll
        for (int kk = 0; kk < 8; kk++) {
            float ra[8], rb[8];
            *(float4*)(ra)   = *(const float4*)(&As[kk][ty*8]);
            *(float4*)(ra+4) = *(const float4*)(&As[kk][ty*8+4]);
            *(float4*)(rb)   = *(const float4*)(&Bs[kk][tx*8]);
            *(float4*)(rb+4) = *(const float4*)(&Bs[kk][tx*8+4]);
            #pragma unroll
            for (int i = 0; i < 8; i++)
                #pragma unroll
                for (int j = 0; j < 8; j++)
                    acc[i][j] = fmaf(ra[i], rb[j], acc[i][j]);
        }
        __syncthreads();
    }

    int colBase = blockIdx.x*128 + tx*8;
    float bv[8];
    #pragma unroll
    for (int j = 0; j < 8; j++) bv[j] = bias ? bias[colBase + j] : 0.f;
    #pragma unroll
    for (int i = 0; i < 8; i++) {
        size_t row = (size_t)blockIdx.y*128 + ty*8 + i;
        float4* cp = (float4*)(C + row*(size_t)N + colBase);
        cp[0] = make_float4(acc[i][0]+bv[0], acc[i][1]+bv[1], acc[i][2]+bv[2], acc[i][3]+bv[3]);
        cp[1] = make_float4(acc[i][4]+bv[4], acc[i][5]+bv[5], acc[i][6]+bv[6], acc[i][7]+bv[7]);
    }
}

// ---------------- persistent LSTM recurrence: 128 CTAs x 256 thr ----------------
// warp w: hout = blk*4 + (w&3), K-half = w>>2.  Lane b<16 of warps 0-3 owns state (b,hout).
__global__ __launch_bounds__(256,1) void k_lstm(const float* __restrict__ init_h,
                                                const float* __restrict__ init_c,
                                                const float* __restrict__ W_ih,
                                                const float* __restrict__ W_hh) {
    __shared__ float sx[BB*HH];       // 32 KB
    __shared__ float4 sred[128];      // [warp][lane<16]
    int tid = threadIdx.x, lane = tid & 31, wid = tid >> 5;
    int hout  = blockIdx.x*4 + (wid & 3);
    int khalf = wid >> 2;

    for (int i = blockIdx.x*256 + tid; i < BB*HH; i += gridDim.x*256) {
        int b = i >> 9, h = i & 511;
        g_h0[0][i] = init_h[b*1024 + h];
        g_h1[0][i] = init_h[b*1024 + 512 + h];
        g_c0[i]    = init_c[b*1024 + h];
        g_c1[i]    = init_c[b*1024 + 512 + h];
    }
    gbar();

    for (int t = 0; t < TT; t++) {
        int p = t & 1, q = p ^ 1;

        // ===== layer 0: gates = gx0 + (0.5 h0)@Whh0^T + K0 =====
        {
            const float4* s = (const float4*)g_h0[p];
            float4* d = (float4*)sx;
            for (int i = tid; i < BB*HH/4; i += 256) {
                float4 v = s[i];
                v.x*=0.5f; v.y*=0.5f; v.z*=0.5f; v.w*=0.5f;
                d[i] = v;
            }
        }
        __syncthreads();

        float acc[4][16];
        #pragma unroll
        for (int c = 0; c < 4; c++)
            #pragma unroll
            for (int b = 0; b < 16; b++) acc[c][b] = 0.f;

        {
            const float* W0 = W_hh + (size_t)hout*HH;
            #pragma unroll 2
            for (int kk = 0; kk < 8; kk++) {
                int k = khalf*256 + kk*32 + lane;
                float w0 = W0[k], w1 = W0[262144+k], w2 = W0[524288+k], w3 = W0[786432+k];
                #pragma unroll
                for (int b = 0; b < 16; b++) {
                    float xv = sx[b*HH + k];
                    acc[0][b] = fmaf(w0, xv, acc[0][b]);
                    acc[1][b] = fmaf(w1, xv, acc[1][b]);
                    acc[2][b] = fmaf(w2, xv, acc[2][b]);
                    acc[3][b] = fmaf(w3, xv, acc[3][b]);
                }
            }
        }
        #pragma unroll
        for (int c = 0; c < 4; c++)
            #pragma unroll
            for (int b = 0; b < 16; b++)
                #pragma unroll
                for (int o = 16; o > 0; o >>= 1)
                    acc[c][b] += __shfl_xor_sync(0xffffffffu, acc[c][b], o);
        {
            float r0=0,r1=0,r2=0,r3=0;
            #pragma unroll
            for (int b = 0; b < 16; b++)
                if (lane == b) { r0=acc[0][b]; r1=acc[1][b]; r2=acc[2][b]; r3=acc[3][b]; }
            if (lane < 16) sred[wid*16 + lane] = make_float4(r0,r1,r2,r3);
        }
        __syncthreads();
        if (wid < 4 && lane < 16) {
            int b = lane;
            float4 pa = sred[wid*16 + b], pb = sred[(wid+4)*16 + b];
            const float* Kp = g_K + b*G4;
            const float* gx = g_gx0 + ((size_t)(b*TT + t))*G4;
            float iv = pa.x+pb.x + Kp[hout]      + gx[hout];
            float fv = pa.y+pb.y + Kp[hout+512]  + gx[hout+512];
            float gv = pa.z+pb.z + Kp[hout+1024] + gx[hout+1024];
            float ov = pa.w+pb.w + Kp[hout+1536] + gx[hout+1536];
            float cn = sigf(fv)*g_c0[b*HH+hout] + sigf(iv)*tanhf(gv);
            g_c0[b*HH+hout] = cn;
            g_h0[q][b*HH+hout] = sigf(ov)*tanhf(cn);
        }
        gbar();

        // ===== layer 1: gates = h0new@Wih1^T + (0.5 h1)@Whh1^T + K1 =====
        {
            const float4* s = (const float4*)g_h0[q];
            float4* d = (float4*)sx;
            for (int i = tid; i < BB*HH/4; i += 256) d[i] = s[i];
        }
        __syncthreads();

        #pragma unroll
        for (int c = 0; c < 4; c++)
            #pragma unroll
            for (int b = 0; b < 16; b++) acc[c][b] = 0.f;
        {
            const float* Wi = W_ih + 1048576 + (size_t)hout*HH;
            #pragma unroll 2
            for (int kk = 0; kk < 8; kk++) {
                int k = khalf*256 + kk*32 + lane;
                float w0 = Wi[k], w1 = Wi[262144+k], w2 = Wi[524288+k], w3 = Wi[786432+k];
                #pragma unroll
                for (int b = 0; b < 16; b++) {
                    float xv = sx[b*HH + k];
                    acc[0][b] = fmaf(w0, xv, acc[0][b]);
                    acc[1][b] = fmaf(w1, xv, acc[1][b]);
                    acc[2][b] = fmaf(w2, xv, acc[2][b]);
                    acc[3][b] = fmaf(w3, xv, acc[3][b]);
                }
            }
        }
        __syncthreads();   // all reads of sx (phase A) done
        {
            const float4* s = (const float4*)g_h1[p];
            float4* d = (float4*)sx;
            for (int i = tid; i < BB*HH/4; i += 256) {
                float4 v = s[i];
                v.x*=0.5f; v.y*=0.5f; v.z*=0.5f; v.w*=0.5f;
                d[i] = v;
            }
        }
        __syncthreads();
        {
            const float* W1h = W_hh + 1048576 + (size_t)hout*HH;
            #pragma unroll 2
            for (int kk = 0; kk < 8; kk++) {
                int k = khalf*256 + kk*32 + lane;
                float w0 = W1h[k], w1 = W1h[262144+k], w2 = W1h[524288+k], w3 = W1h[786432+k];
                #pragma unroll
                for (int b = 0; b < 16; b++) {
                    float xv = sx[b*HH + k];
                    acc[0][b] = fmaf(w0, xv, acc[0][b]);
                    acc[1][b] = fmaf(w1, xv, acc[1][b]);
                    acc[2][b] = fmaf(w2, xv, acc[2][b]);
                    acc[3][b] = fmaf(w3, xv, acc[3][b]);
                }
            }
        }
        #pragma unroll
        for (int c = 0; c < 4; c++)
            #pragma unroll
            for (int b = 0; b < 16; b++)
                #pragma unroll
                for (int o = 16; o > 0; o >>= 1)
                    acc[c][b] += __shfl_xor_sync(0xffffffffu, acc[c][b], o);
        {
            float r0=0,r1=0,r2=0,r3=0;
            #pragma unroll
            for (int b = 0; b < 16; b++)
                if (lane == b) { r0=acc[0][b]; r1=acc[1][b]; r2=acc[2][b]; r3=acc[3][b]; }
            if (lane < 16) sred[wid*16 + lane] = make_float4(r0,r1,r2,r3);
        }
        __syncthreads();
        if (wid < 4 && lane < 16) {
            int b = lane;
            float4 pa = sred[wid*16 + b], pb = sred[(wid+4)*16 + b];
            const float* Kp = g_K + 32768 + b*G4;
            float iv = pa.x+pb.x + Kp[hout];
            float fv = pa.y+pb.y + Kp[hout+512];
            float gv = pa.z+pb.z + Kp[hout+1024];
            float ov = pa.w+pb.w + Kp[hout+1536];
            float cn = sigf(fv)*g_c1[b*HH+hout] + sigf(iv)*tanhf(gv);
            g_c1[b*HH+hout] = cn;
            float hn = sigf(ov)*tanhf(cn);
            g_h1[q][b*HH+hout] = hn;
            g_X[((size_t)(b*TT + t))*HH + hout] = hn;
        }
        gbar();
    }
}

// ---------------- per-row max + argmax over V ----------------
__global__ void k_argmax(const float* __restrict__ logits) {
    __shared__ float sm[256];
    __shared__ int   si[256];
    int r = blockIdx.x, tid = threadIdx.x;
    const float* row = logits + (size_t)r*VV;
    float bm = -1e30f; int bi = 0;
    for (int j = tid; j < VV; j += 256) {
        float v = row[j];
        if (v > bm || (v == bm && j < bi)) { bm = v; bi = j; }
    }
    sm[tid] = bm; si[tid] = bi;
    __syncthreads();
    for (int s = 128; s > 0; s >>= 1) {
        if (tid < s) {
            float v = sm[tid+s]; int i2 = si[tid+s];
            if (v > sm[tid] || (v == sm[tid] && i2 < si[tid])) { sm[tid] = v; si[tid] = i2; }
        }
        __syncthreads();
    }
    if (tid == 0) { g_rowmax[r] = sm[0]; g_argidx[r] = si[0]; }
}

// ---------------- sequential EOS scan + ids output ----------------
__global__ void k_eos(float* __restrict__ ids_out) {
    int b = threadIdx.x;
    if (b >= BB) return;
    int eos = 0;
    for (int t = 0; t < TT; t++) {
        int r = b*TT + t;
        int id = g_argidx[r];
        if (eos) { g_mask[r] = 1; id = PAD_ID; }
        else       g_mask[r] = 0;
        if (ids_out) ids_out[r] = (float)id;
        if (id == EOS_ID) eos = 1;
    }
}

// ---------------- in-place softmax / one-hot masking ----------------
__global__ void k_softmax(float* __restrict__ probs) {
    __shared__ float ss[256];
    int r = blockIdx.x, tid = threadIdx.x;
    float* row = probs + (size_t)r*VV;
    if (g_mask[r]) {
        float4 z = make_float4(0.f,0.f,0.f,0.f);
        for (int j4 = tid; j4 < VV/4; j4 += 256) ((float4*)row)[j4] = z;
        if (tid == 0) row[PAD_ID] = 1.0f;
        return;
    }
    float m = g_rowmax[r];
    float s = 0.f;
    for (int j4 = tid; j4 < VV/4; j4 += 256) {
        float4 v = ((float4*)row)[j4];
        s += __expf(v.x-m) + __expf(v.y-m) + __expf(v.z-m) + __expf(v.w-m);
    }
    ss[tid] = s;
    __syncthreads();
    for (int st = 128; st > 0; st >>= 1) {
        if (tid < st) ss[tid] += ss[tid+st];
        __syncthreads();
    }
    float inv = 1.0f / ss[0];
    for (int j4 = tid; j4 < VV/4; j4 += 256) {
        float4 v = ((float4*)row)[j4];
        v.x = __expf(v.x-m)*inv; v.y = __expf(v.y-m)*inv;
        v.z = __expf(v.z-m)*inv; v.w = __expf(v.w-m)*inv;
        ((float4*)row)[j4] = v;
    }
}

extern "C" void kernel_launch(void* const* d_in, const int* in_sizes, int n_in,
                              void* d_out, int out_size) {
    const float* init_h  = (const float*)d_in[0];
    const float* init_c  = (const float*)d_in[1];
    const int*   init_in = (const int*)d_in[2];
    const int*   targets = (const int*)d_in[3];
    const float* emb     = (const float*)d_in[4];
    const float* embW    = (const float*)d_in[5];
    const float* W_ih    = (const float*)d_in[6];
    const float* W_hh    = (const float*)d_in[7];
    const float* b_ih    = (const float*)d_in[8];
    const float* b_hh    = (const float*)d_in[9];
    const float* W_out   = (const float*)d_in[10];
    const float* b_out   = (const float*)d_in[11];
    const float* aW1     = (const float*)d_in[12];
    const float* ab1     = (const float*)d_in[13];
    const float* aW2     = (const float*)d_in[14];
    const float* ab2     = (const float*)d_in[15];
    float* out = (float*)d_out;
    float* ids_out = ((size_t)out_size >= BTV + (size_t)NROW) ? out + BTV : nullptr;

    k_attn_scores<<<BB*DD*LL, AH>>>(emb, aW1, ab1, aW2, ab2);
    k_attn_ctx<<<BB*LL, 256>>>(emb);
    k_ctx_gates<<<(LL*BB*G4)/8, 256>>>(W_hh, b_ih, b_hh);
    k_embed<<<(BB*TT*HH/4 + 255)/256, 256>>>(init_in, targets, embW);
    k_sgemm_nt<<<dim3(G4/128, NROW/128), 256>>>(0, W_ih, nullptr, nullptr, G4);
    k_lstm<<<128, 256>>>(init_h, init_c, W_ih, W_hh);
    k_sgemm_nt<<<dim3(VV/128, NROW/128), 256>>>(1, W_out, b_out, out, VV);
    k_argmax<<<NROW, 256>>>(out);
    k_eos<<<1, 32>>>(ids_out);
    k_softmax<<<NROW, 256>>>(out);
}

// round 5
// speedup vs baseline: 1.3379x; 1.3379x over previous
#include <cuda_runtime.h>
#include <cuda_bf16.h>
#include <cstdint>

#define BB   16
#define TT   128
#define VV   32000
#define HH   512
#define LL   2
#define DD   8
#define AH   256
#define G4   2048
#define PAD_ID 0
#define EOS_ID 3
#define NROW (BB*TT)            // 2048
#define BTV  ((size_t)NROW*VV)

// ---------------- device scratch ----------------
__device__ float g_scores[BB*DD*LL];
__device__ float g_ctx[BB*LL*HH];
__device__ float g_K[LL*BB*G4];
__device__ float g_Xe[NROW*HH];
__device__ float g_gx0[(size_t)NROW*G4];
__device__ float g_X[NROW*HH];
__device__ float g_h0[2][BB*HH];
__device__ float g_h1[2][BB*HH];
__device__ float g_c0[BB*HH];
__device__ float g_c1[BB*HH];
__device__ float g_rowmax[NROW];
__device__ int   g_argidx[NROW];
__device__ int   g_mask[NROW];
__device__ unsigned g_bcnt = 0;
__device__ unsigned g_bgen = 0;

__device__ __forceinline__ float sigf(float x){ return 1.0f/(1.0f+__expf(-x)); }

// grid barrier (all CTAs resident)
__device__ __forceinline__ void gbar() {
    __threadfence();
    __syncthreads();
    if (threadIdx.x == 0) {
        volatile unsigned* vg = &g_bgen;
        unsigned g = *vg;
        unsigned a = atomicAdd(&g_bcnt, 1u);
        if (a == gridDim.x - 1u) {
            g_bcnt = 0;
            __threadfence();
            atomicAdd(&g_bgen, 1u);
        } else {
            while (*vg == g) { __nanosleep(64); }
        }
        __threadfence();
    }
    __syncthreads();
}

// ---------------- K1: attention scores  blk=(b*D+d)*L+l ----------------
__global__ void k_attn_scores(const float* __restrict__ emb, const float* __restrict__ W1,
                              const float* __restrict__ b1, const float* __restrict__ W2,
                              const float* __restrict__ b2) {
    __shared__ float se[HH];
    __shared__ float red[AH];
    int blk = blockIdx.x;
    const float* ep = emb + (size_t)blk * HH;
    for (int i = threadIdx.x; i < HH; i += AH) se[i] = ep[i];
    __syncthreads();
    int a = threadIdx.x;
    const float* w1 = W1 + (size_t)a * HH;
    float dot = 0.f;
    #pragma unroll 8
    for (int k = 0; k < HH; k++) dot += se[k] * w1[k];
    red[a] = tanhf(dot + b1[a]) * W2[a];
    __syncthreads();
    for (int s = AH/2; s > 0; s >>= 1) {
        if (a < s) red[a] += red[a + s];
        __syncthreads();
    }
    if (a == 0) g_scores[blk] = red[0] + b2[0];
}

// ---------------- K2: softmax over docs + context ----------------
__global__ void k_attn_ctx(const float* __restrict__ emb) {
    int b = blockIdx.x >> 1, l = blockIdx.x & 1;
    __shared__ float s[DD];
    if (threadIdx.x < DD) s[threadIdx.x] = g_scores[(b*DD + threadIdx.x)*LL + l];
    __syncthreads();
    float mx = -1e30f;
    #pragma unroll
    for (int d = 0; d < DD; d++) mx = fmaxf(mx, s[d]);
    float w[DD]; float sum = 0.f;
    #pragma unroll
    for (int d = 0; d < DD; d++) { w[d] = __expf(s[d] - mx); sum += w[d]; }
    float inv = 1.0f / sum;
    for (int h = threadIdx.x; h < HH; h += 256) {
        float acc = 0.f;
        #pragma unroll
        for (int d = 0; d < DD; d++)
            acc += w[d] * inv * emb[((size_t)(b*DD + d)*LL + l)*HH + h];
        g_ctx[(b*LL + l)*HH + h] = acc;
    }
}

// ---------------- K3: K[l][b][g] = 0.5*ctx@Whh^T + b_ih + b_hh ----------------
__global__ void k_ctx_gates(const float* __restrict__ Whh, const float* __restrict__ bih,
                            const float* __restrict__ bhh) {
    int out  = blockIdx.x * 8 + (threadIdx.x >> 5);
    int lane = threadIdx.x & 31;
    int l = out >> 15;
    int b = (out >> 11) & 15;
    int g = out & 2047;
    const float* wr = Whh + (size_t)l*G4*HH + (size_t)g*HH;
    const float* cx = g_ctx + (b*LL + l)*HH;
    float acc = 0.f;
    for (int k = lane; k < HH; k += 32) acc += wr[k]*cx[k];
    #pragma unroll
    for (int o = 16; o > 0; o >>= 1) acc += __shfl_xor_sync(0xffffffffu, acc, o);
    if (lane == 0) g_K[out] = 0.5f*acc + bih[l*G4 + g] + bhh[l*G4 + g];
}

// ---------------- K4: embedding gather ----------------
__global__ void k_embed(const int* __restrict__ init_input, const int* __restrict__ targets,
                        const float* __restrict__ embW) {
    int i4 = blockIdx.x * 256 + threadIdx.x;       // over B*T*H/4
    if (i4 >= BB*TT*HH/4) return;
    int r  = i4 >> 7;
    int h4 = i4 & 127;
    int b = r >> 7, t = r & 127;
    int tok = (t == 0) ? init_input[b] : targets[b*TT + t - 1];
    ((float4*)g_Xe)[i4] = ((const float4*)(embW + (size_t)tok*HH))[h4];
}

// ---------------- tf32-split tensor-core GEMM (NT) ----------------
// C[M x N] = A[M x 512] * B[N x 512]^T (+bias), fp32 accuracy via hi/lo split.
// CTA tile 128x256, BK=32, 8 warps (2 in M x 4 in N), warp tile 64x64.
__device__ __forceinline__ uint32_t cvt_tf32(float v) {
    uint32_t r; asm("cvt.rna.tf32.f32 %0, %1;" : "=r"(r) : "f"(v)); return r;
}
__device__ __forceinline__ void mma8(float& c0, float& c1, float& c2, float& c3,
                                     uint32_t a0, uint32_t a1, uint32_t a2, uint32_t a3,
                                     uint32_t b0, uint32_t b1) {
    asm volatile("mma.sync.aligned.m16n8k8.row.col.f32.tf32.tf32.f32 "
        "{%0,%1,%2,%3}, {%4,%5,%6,%7}, {%8,%9}, {%0,%1,%2,%3};"
        : "+f"(c0), "+f"(c1), "+f"(c2), "+f"(c3)
        : "r"(a0), "r"(a1), "r"(a2), "r"(a3), "r"(b0), "r"(b1));
}
__device__ __forceinline__ void cpasync16(uint32_t s, const void* g) {
    asm volatile("cp.async.ca.shared.global [%0], [%1], 16;" :: "r"(s), "l"(g));
}

#define ASTR 36
#define ABUF (128*ASTR)
#define BBUF (256*ASTR)
#define STG  (ABUF + BBUF)

__global__ __launch_bounds__(256) void k_mma_nt(const float* __restrict__ A,
        const float* __restrict__ Bw, const float* __restrict__ bias,
        float* __restrict__ C, int N) {
    extern __shared__ float sm[];
    int tid = threadIdx.x, lane = tid & 31, wid = tid >> 5;
    int wm = wid & 1, wn = wid >> 1;
    size_t bm = (size_t)blockIdx.y * 128;
    size_t bn = (size_t)blockIdx.x * 256;

    int sc   = (tid & 7) * 4;     // k offset within BK
    int srow = tid >> 3;          // 0..31
    const float* Ag = A  + (bm + srow) * 512 + sc;
    const float* Bg = Bw + (bn + srow) * 512 + sc;
    uint32_t smem_base = (uint32_t)__cvta_generic_to_shared(sm);

    float acc[4][8][4];
    #pragma unroll
    for (int i = 0; i < 4; i++)
        #pragma unroll
        for (int j = 0; j < 8; j++)
            #pragma unroll
            for (int r = 0; r < 4; r++) acc[i][j][r] = 0.f;

    // stage kt=0
    {
        uint32_t ad = smem_base + (uint32_t)(srow*ASTR + sc)*4u;
        uint32_t bd = smem_base + (uint32_t)(ABUF + srow*ASTR + sc)*4u;
        #pragma unroll
        for (int i = 0; i < 4; i++) cpasync16(ad + i*32*ASTR*4, Ag + i*32*512);
        #pragma unroll
        for (int i = 0; i < 8; i++) cpasync16(bd + i*32*ASTR*4, Bg + i*32*512);
        asm volatile("cp.async.commit_group;");
    }

    for (int kt = 0; kt < 16; kt++) {
        if (kt + 1 < 16) {
            int buf = (kt + 1) & 1;
            uint32_t ad = smem_base + (uint32_t)(buf*STG + srow*ASTR + sc)*4u;
            uint32_t bd = smem_base + (uint32_t)(buf*STG + ABUF + srow*ASTR + sc)*4u;
            const float* ag = Ag + (kt+1)*32;
            const float* bg = Bg + (kt+1)*32;
            #pragma unroll
            for (int i = 0; i < 4; i++) cpasync16(ad + i*32*ASTR*4, ag + i*32*512);
            #pragma unroll
            for (int i = 0; i < 8; i++) cpasync16(bd + i*32*ASTR*4, bg + i*32*512);
            asm volatile("cp.async.commit_group;");
            asm volatile("cp.async.wait_group 1;");
        } else {
            asm volatile("cp.async.wait_group 0;");
        }
        __syncthreads();
        const float* Ab = sm + (kt & 1)*STG;
        const float* Bb = Ab + ABUF;

        #pragma unroll
        for (int ks = 0; ks < 4; ks++) {
            int ar = wm*64 + (lane >> 2);
            int ck = ks*8 + (lane & 3);
            uint32_t ah[4][4], al[4][4];
            #pragma unroll
            for (int mt = 0; mt < 4; mt++) {
                int base = (ar + mt*16)*ASTR + ck;
                float v0 = Ab[base], v1 = Ab[base + 8*ASTR];
                float v2 = Ab[base + 4], v3 = Ab[base + 8*ASTR + 4];
                ah[mt][0] = cvt_tf32(v0); al[mt][0] = __float_as_uint(v0 - __uint_as_float(ah[mt][0]));
                ah[mt][1] = cvt_tf32(v1); al[mt][1] = __float_as_uint(v1 - __uint_as_float(ah[mt][1]));
                ah[mt][2] = cvt_tf32(v2); al[mt][2] = __float_as_uint(v2 - __uint_as_float(ah[mt][2]));
                ah[mt][3] = cvt_tf32(v3); al[mt][3] = __float_as_uint(v3 - __uint_as_float(ah[mt][3]));
            }
            int br = wn*64 + (lane >> 2);
            #pragma unroll
            for (int half = 0; half < 2; half++) {
                uint32_t bh[4][2], bl[4][2];
                #pragma unroll
                for (int j = 0; j < 4; j++) {
                    int nt = half*4 + j;
                    int base = (br + nt*8)*ASTR + ck;
                    float v0 = Bb[base], v1 = Bb[base + 4];
                    bh[j][0] = cvt_tf32(v0); bl[j][0] = __float_as_uint(v0 - __uint_as_float(bh[j][0]));
                    bh[j][1] = cvt_tf32(v1); bl[j][1] = __float_as_uint(v1 - __uint_as_float(bh[j][1]));
                }
                #pragma unroll
                for (int mt = 0; mt < 4; mt++)
                    #pragma unroll
                    for (int j = 0; j < 4; j++) {
                        float* c = acc[mt][half*4 + j];
                        mma8(c[0], c[1], c[2], c[3], ah[mt][0], ah[mt][1], ah[mt][2], ah[mt][3], bh[j][0], bh[j][1]);
                        mma8(c[0], c[1], c[2], c[3], ah[mt][0], ah[mt][1], ah[mt][2], ah[mt][3], bl[j][0], bl[j][1]);
                        mma8(c[0], c[1], c[2], c[3], al[mt][0], al[mt][1], al[mt][2], al[mt][3], bh[j][0], bh[j][1]);
                    }
            }
        }
        __syncthreads();
    }

    #pragma unroll
    for (int mt = 0; mt < 4; mt++) {
        size_t r0 = bm + wm*64 + mt*16 + (lane >> 2);
        #pragma unroll
        for (int nt = 0; nt < 8; nt++) {
            size_t c0 = bn + wn*64 + nt*8 + (lane & 3)*2;
            float b0 = bias ? bias[c0] : 0.f;
            float b1 = bias ? bias[c0 + 1] : 0.f;
            *(float2*)&C[r0*(size_t)N + c0] =
                make_float2(acc[mt][nt][0] + b0, acc[mt][nt][1] + b1);
            *(float2*)&C[(r0 + 8)*(size_t)N + c0] =
                make_float2(acc[mt][nt][2] + b0, acc[mt][nt][3] + b1);
        }
    }
}

// ---------------- fused persistent LSTM: 1 barrier per segment ----------------
// segment s: L0(t=s) [s<T] and L1(t=s-1) [s>=1]; both read g_h0[s&1].
__global__ __launch_bounds__(256,1) void k_lstm(const float* __restrict__ init_h,
                                                const float* __restrict__ init_c,
                                                const float* __restrict__ W_ih,
                                                const float* __restrict__ W_hh) {
    __shared__ float4 sredA[128];
    __shared__ float4 sredB[128];
    int tid = threadIdx.x, lane = tid & 31, wid = tid >> 5;
    int hout  = blockIdx.x*4 + (wid & 3);
    int khalf = wid >> 2;

    for (int i = blockIdx.x*256 + tid; i < BB*HH; i += gridDim.x*256) {
        int b = i >> 9, h = i & 511;
        g_h0[0][i] = init_h[b*1024 + h];
        g_h1[0][i] = init_h[b*1024 + 512 + h];
        g_c0[i]    = init_c[b*1024 + h];
        g_c1[i]    = init_c[b*1024 + 512 + h];
    }
    gbar();

    const float* W0  = W_hh + (size_t)hout*HH;                 // layer0 Whh
    const float* Wi1 = W_ih + 1048576 + (size_t)hout*HH;       // layer1 Wih
    const float* Wh1 = W_hh + 1048576 + (size_t)hout*HH;       // layer1 Whh

    for (int s = 0; s <= TT; s++) {
        int p0 = s & 1;
        bool doL0 = (s < TT), doL1 = (s >= 1);
        float s0 = doL0 ? 0.5f : 0.0f;   // fold ALPHA mix scale into weights
        float s1 = doL1 ? 1.0f : 0.0f;
        float sh = doL1 ? 0.5f : 0.0f;
        const float* h0p = g_h0[p0];
        const float* h1p = g_h1[doL1 ? ((s - 1) & 1) : 0];

        float accA[4][16], accB[4][16];
        #pragma unroll
        for (int c = 0; c < 4; c++)
            #pragma unroll
            for (int b = 0; b < 16; b++) { accA[c][b] = 0.f; accB[c][b] = 0.f; }

        #pragma unroll 2
        for (int kk = 0; kk < 8; kk++) {
            int k = khalf*256 + kk*32 + lane;
            float w0 = s0*W0[k],         w1 = s0*W0[262144+k];
            float w2 = s0*W0[524288+k],  w3 = s0*W0[786432+k];
            float u0 = s1*Wi1[k],        u1 = s1*Wi1[262144+k];
            float u2 = s1*Wi1[524288+k], u3 = s1*Wi1[786432+k];
            #pragma unroll
            for (int b = 0; b < 16; b++) {
                float xv = h0p[b*HH + k];
                accA[0][b] = fmaf(w0, xv, accA[0][b]);
                accA[1][b] = fmaf(w1, xv, accA[1][b]);
                accA[2][b] = fmaf(w2, xv, accA[2][b]);
                accA[3][b] = fmaf(w3, xv, accA[3][b]);
                accB[0][b] = fmaf(u0, xv, accB[0][b]);
                accB[1][b] = fmaf(u1, xv, accB[1][b]);
                accB[2][b] = fmaf(u2, xv, accB[2][b]);
                accB[3][b] = fmaf(u3, xv, accB[3][b]);
            }
        }
        #pragma unroll 2
        for (int kk = 0; kk < 8; kk++) {
            int k = khalf*256 + kk*32 + lane;
            float v0 = sh*Wh1[k],        v1 = sh*Wh1[262144+k];
            float v2 = sh*Wh1[524288+k], v3 = sh*Wh1[786432+k];
            #pragma unroll
            for (int b = 0; b < 16; b++) {
                float hv = h1p[b*HH + k];
                accB[0][b] = fmaf(v0, hv, accB[0][b]);
                accB[1][b] = fmaf(v1, hv, accB[1][b]);
                accB[2][b] = fmaf(v2, hv, accB[2][b]);
                accB[3][b] = fmaf(v3, hv, accB[3][b]);
            }
        }
        #pragma unroll
        for (int c = 0; c < 4; c++)
            #pragma unroll
            for (int b = 0; b < 16; b++)
                #pragma unroll
                for (int o = 16; o > 0; o >>= 1) {
                    accA[c][b] += __shfl_xor_sync(0xffffffffu, accA[c][b], o);
                    accB[c][b] += __shfl_xor_sync(0xffffffffu, accB[c][b], o);
                }
        {
            float a0=0,a1=0,a2=0,a3=0, b0v=0,b1v=0,b2v=0,b3v=0;
            #pragma unroll
            for (int b = 0; b < 16; b++)
                if (lane == b) {
                    a0=accA[0][b]; a1=accA[1][b]; a2=accA[2][b]; a3=accA[3][b];
                    b0v=accB[0][b]; b1v=accB[1][b]; b2v=accB[2][b]; b3v=accB[3][b];
                }
            if (lane < 16) {
                sredA[wid*16 + lane] = make_float4(a0,a1,a2,a3);
                sredB[wid*16 + lane] = make_float4(b0v,b1v,b2v,b3v);
            }
        }
        __syncthreads();
        if (wid < 4 && lane < 16) {
            int b = lane;
            int si = b*HH + hout;
            if (doL0) {
                float4 pa = sredA[wid*16 + b], pb = sredA[(wid+4)*16 + b];
                const float* Kp = g_K + b*G4;
                const float* gx = g_gx0 + ((size_t)(b*TT + s))*G4;
                float iv = pa.x+pb.x + Kp[hout]      + gx[hout];
                float fv = pa.y+pb.y + Kp[hout+512]  + gx[hout+512];
                float gv = pa.z+pb.z + Kp[hout+1024] + gx[hout+1024];
                float ov = pa.w+pb.w + Kp[hout+1536] + gx[hout+1536];
                float cn = sigf(fv)*g_c0[si] + sigf(iv)*tanhf(gv);
                g_c0[si] = cn;
                g_h0[p0^1][si] = sigf(ov)*tanhf(cn);
            }
            if (doL1) {
                float4 pa = sredB[wid*16 + b], pb = sredB[(wid+4)*16 + b];
                const float* Kp = g_K + 32768 + b*G4;
                float iv = pa.x+pb.x + Kp[hout];
                float fv = pa.y+pb.y + Kp[hout+512];
                float gv = pa.z+pb.z + Kp[hout+1024];
                float ov = pa.w+pb.w + Kp[hout+1536];
                float cn = sigf(fv)*g_c1[si] + sigf(iv)*tanhf(gv);
                g_c1[si] = cn;
                float hn = sigf(ov)*tanhf(cn);
                g_h1[s & 1][si] = hn;
                g_X[((size_t)(b*TT + (s-1)))*HH + hout] = hn;
            }
        }
        gbar();
    }
}

// ---------------- per-row max + argmax over V ----------------
__global__ void k_argmax(const float* __restrict__ logits) {
    __shared__ float sm[256];
    __shared__ int   si[256];
    int r = blockIdx.x, tid = threadIdx.x;
    const float* row = logits + (size_t)r*VV;
    float bm = -1e30f; int bi = 0;
    for (int j = tid; j < VV; j += 256) {
        float v = row[j];
        if (v > bm || (v == bm && j < bi)) { bm = v; bi = j; }
    }
    sm[tid] = bm; si[tid] = bi;
    __syncthreads();
    for (int s = 128; s > 0; s >>= 1) {
        if (tid < s) {
            float v = sm[tid+s]; int i2 = si[tid+s];
            if (v > sm[tid] || (v == sm[tid] && i2 < si[tid])) { sm[tid] = v; si[tid] = i2; }
        }
        __syncthreads();
    }
    if (tid == 0) { g_rowmax[r] = sm[0]; g_argidx[r] = si[0]; }
}

// ---------------- sequential EOS scan + ids output ----------------
__global__ void k_eos(float* __restrict__ ids_out) {
    int b = threadIdx.x;
    if (b >= BB) return;
    int eos = 0;
    for (int t = 0; t < TT; t++) {
        int r = b*TT + t;
        int id = g_argidx[r];
        if (eos) { g_mask[r] = 1; id = PAD_ID; }
        else       g_mask[r] = 0;
        if (ids_out) ids_out[r] = (float)id;
        if (id == EOS_ID) eos = 1;
    }
}

// ---------------- in-place softmax / one-hot masking ----------------
__global__ void k_softmax(float* __restrict__ probs) {
    __shared__ float ss[256];
    int r = blockIdx.x, tid = threadIdx.x;
    float* row = probs + (size_t)r*VV;
    if (g_mask[r]) {
        float4 z = make_float4(0.f,0.f,0.f,0.f);
        for (int j4 = tid; j4 < VV/4; j4 += 256) ((float4*)row)[j4] = z;
        if (tid == 0) row[PAD_ID] = 1.0f;
        return;
    }
    float m = g_rowmax[r];
    float s = 0.f;
    for (int j4 = tid; j4 < VV/4; j4 += 256) {
        float4 v = ((float4*)row)[j4];
        s += __expf(v.x-m) + __expf(v.y-m) + __expf(v.z-m) + __expf(v.w-m);
    }
    ss[tid] = s;
    __syncthreads();
    for (int st = 128; st > 0; st >>= 1) {
        if (tid < st) ss[tid] += ss[tid+st];
        __syncthreads();
    }
    float inv = 1.0f / ss[0];
    for (int j4 = tid; j4 < VV/4; j4 += 256) {
        float4 v = ((float4*)row)[j4];
        v.x = __expf(v.x-m)*inv; v.y = __expf(v.y-m)*inv;
        v.z = __expf(v.z-m)*inv; v.w = __expf(v.w-m)*inv;
        ((float4*)row)[j4] = v;
    }
}

extern "C" void kernel_launch(void* const* d_in, const int* in_sizes, int n_in,
                              void* d_out, int out_size) {
    const float* init_h  = (const float*)d_in[0];
    const float* init_c  = (const float*)d_in[1];
    const int*   init_in = (const int*)d_in[2];
    const int*   targets = (const int*)d_in[3];
    const float* emb     = (const float*)d_in[4];
    const float* embW    = (const float*)d_in[5];
    const float* W_ih    = (const float*)d_in[6];
    const float* W_hh    = (const float*)d_in[7];
    const float* b_ih    = (const float*)d_in[8];
    const float* b_hh    = (const float*)d_in[9];
    const float* W_out   = (const float*)d_in[10];
    const float* b_out   = (const float*)d_in[11];
    const float* aW1     = (const float*)d_in[12];
    const float* ab1     = (const float*)d_in[13];
    const float* aW2     = (const float*)d_in[14];
    const float* ab2     = (const float*)d_in[15];
    float* out = (float*)d_out;
    float* ids_out = ((size_t)out_size >= BTV + (size_t)NROW) ? out + BTV : nullptr;

    static bool attr_done = false;
    if (!attr_done) {
        cudaFuncSetAttribute(k_mma_nt, cudaFuncAttributeMaxDynamicSharedMemorySize,
                             2*STG*(int)sizeof(float));
        attr_done = true;
    }
    float *Xep = nullptr, *gx0p = nullptr, *Xp = nullptr;
    cudaGetSymbolAddress((void**)&Xep,  g_Xe);
    cudaGetSymbolAddress((void**)&gx0p, g_gx0);
    cudaGetSymbolAddress((void**)&Xp,   g_X);

    k_attn_scores<<<BB*DD*LL, AH>>>(emb, aW1, ab1, aW2, ab2);
    k_attn_ctx<<<BB*LL, 256>>>(emb);
    k_ctx_gates<<<(LL*BB*G4)/8, 256>>>(W_hh, b_ih, b_hh);
    k_embed<<<(BB*TT*HH/4 + 255)/256, 256>>>(init_in, targets, embW);
    k_mma_nt<<<dim3(G4/256, NROW/128), 256, 2*STG*sizeof(float)>>>(
        Xep, W_ih, nullptr, gx0p, G4);
    k_lstm<<<128, 256>>>(init_h, init_c, W_ih, W_hh);
    k_mma_nt<<<dim3(VV/256, NROW/128), 256, 2*STG*sizeof(float)>>>(
        Xp, W_out, b_out, out, VV);
    k_argmax<<<NROW, 256>>>(out);
    k_eos<<<1, 32>>>(ids_out);
    k_softmax<<<NROW, 256>>>(out);
}